// round 4
// baseline (speedup 1.0000x reference)
#include <cuda_runtime.h>
#include <cuda_bf16.h>

// Max pairs for insnum=3000: 3000*3000-3000 = 8,997,000 (divisible by 4).
#define MAX_PAIRS 9000000

// Static scratch: one byte per pair row, low 4 bits = class-bit mask.
// Zero-initialized at module load; loss_kernel cleans it after reading, so it
// is zero again at the start of every subsequent kernel_launch/graph replay.
__device__ unsigned char g_mask[MAX_PAIRS];

// ---------------------------------------------------------------------------
// type table: _SUPPORT -> 1, _PROXIMITY -> 2, _COMPARATIVE -> 3, else 0
// ---------------------------------------------------------------------------
__device__ __forceinline__ int type_of_pred(int p) {
    if (p == 1 || (p >= 14 && p <= 26)) return 1;
    if (p >= 2 && p <= 7)               return 2;
    if (p >= 8 && p <= 13)              return 3;
    return 0;
}

// ---------------------------------------------------------------------------
// Kernel 1: scatter relation class bits into the mask; also zero the output
// scalar (safe: runs before loss_kernel's atomicAdds in stream order).
// ---------------------------------------------------------------------------
__global__ void scatter_kernel(const int* __restrict__ rel, int n_rel,
                               int insnum, int n_pairs,
                               float* __restrict__ out) {
    int r = blockIdx.x * blockDim.x + threadIdx.x;
    if (r == 0) *out = 0.0f;
    if (r >= n_rel) return;
    int i = rel[3 * r + 0];
    int j = rel[3 * r + 1];
    int p = rel[3 * r + 2];
    if (i == j) return;
    p = min(max(p, 0), 63);
    int t = type_of_pred(p);
    long long flat = (long long)i * (insnum - 1) + j - (i < j ? 1 : 0);
    if ((unsigned long long)flat >= (unsigned long long)n_pairs) return;
    unsigned int* word = reinterpret_cast<unsigned int*>(g_mask) + (flat >> 2);
    unsigned int bit = (1u << t) << ((flat & 3) * 8);
    atomicOr(word, bit);
}

// ---------------------------------------------------------------------------
// Kernel 2: per-4-row focal loss + reduction + mask self-clean.
//   Each thread handles 4 consecutive rows per loop iteration:
//   1x uint mask word + 4x float4 logits (64B contiguous) -> MLP=5.
// ---------------------------------------------------------------------------
__device__ __forceinline__ float row_loss(float4 x, unsigned int m,
                                          float a0, float a1, float a2, float a3) {
    if (m == 0u) m = 1u;  // empty row -> class 0
    float mx = fmaxf(fmaxf(x.x, x.y), fmaxf(x.z, x.w));
    float e0 = __expf(x.x - mx);
    float e1 = __expf(x.y - mx);
    float e2 = __expf(x.z - mx);
    float e3 = __expf(x.w - mx);
    float S = e0 + e1 + e2 + e3;

    float ms = 0.0f, alpha = 0.0f;
    if (m & 1u) { ms += e0; alpha += a0; }
    if (m & 2u) { ms += e1; alpha += a1; }
    if (m & 4u) { ms += e2; alpha += a2; }
    if (m & 8u) { ms += e3; alpha += a3; }

    float p  = __fdividef(ms, S);
    float om = 1.0f - p;
    return -alpha * om * om * __logf(p);
}

__global__ void loss_kernel(const float4* __restrict__ logits,
                            const float* __restrict__ pred_w,
                            float* __restrict__ out,
                            int n_words4, int n_pairs, float inv_n) {
    const float a0 = __ldg(&pred_w[0]);
    const float a1 = __ldg(&pred_w[1]);
    const float a2 = __ldg(&pred_w[2]);
    const float a3 = __ldg(&pred_w[3]);

    unsigned int* mask_words = reinterpret_cast<unsigned int*>(g_mask);

    float acc = 0.0f;
    for (int w = blockIdx.x * blockDim.x + threadIdx.x; w < n_words4;
         w += gridDim.x * blockDim.x) {
        int r0 = w * 4;
        unsigned int mw = mask_words[w];

        // 4 contiguous float4 loads (64B per thread)
        float4 x0 = __ldg(&logits[r0 + 0]);
        float4 x1 = __ldg(&logits[r0 + 1]);
        float4 x2 = __ldg(&logits[r0 + 2]);
        float4 x3 = __ldg(&logits[r0 + 3]);

        // self-clean for the next launch/replay
        mask_words[w] = 0u;

        if (r0 + 3 < n_pairs) {
            acc += row_loss(x0, (mw      ) & 0xffu, a0, a1, a2, a3);
            acc += row_loss(x1, (mw >>  8) & 0xffu, a0, a1, a2, a3);
            acc += row_loss(x2, (mw >> 16) & 0xffu, a0, a1, a2, a3);
            acc += row_loss(x3, (mw >> 24) & 0xffu, a0, a1, a2, a3);
        } else {
            // tail word (only if n_pairs % 4 != 0)
            if (r0 + 0 < n_pairs) acc += row_loss(x0, (mw      ) & 0xffu, a0, a1, a2, a3);
            if (r0 + 1 < n_pairs) acc += row_loss(x1, (mw >>  8) & 0xffu, a0, a1, a2, a3);
            if (r0 + 2 < n_pairs) acc += row_loss(x2, (mw >> 16) & 0xffu, a0, a1, a2, a3);
        }
    }

    // warp reduce
    #pragma unroll
    for (int o = 16; o > 0; o >>= 1)
        acc += __shfl_xor_sync(0xffffffffu, acc, o);

    __shared__ float smem[32];
    int lane = threadIdx.x & 31;
    int wid  = threadIdx.x >> 5;
    if (lane == 0) smem[wid] = acc;
    __syncthreads();

    int nwarps = blockDim.x >> 5;
    if (wid == 0) {
        float v = (lane < nwarps) ? smem[lane] : 0.0f;
        #pragma unroll
        for (int o = 16; o > 0; o >>= 1)
            v += __shfl_xor_sync(0xffffffffu, v, o);
        if (lane == 0)
            atomicAdd(out, v * inv_n);
    }
}

// ---------------------------------------------------------------------------
// Launch
// ---------------------------------------------------------------------------
extern "C" void kernel_launch(void* const* d_in, const int* in_sizes, int n_in,
                              void* d_out, int out_size) {
    const float* type_output = (const float*)d_in[0];
    const int*   rel_gt      = (const int*)d_in[2];
    const float* pred_w      = (const float*)d_in[3];

    int insnum  = in_sizes[1];
    int n_rel   = in_sizes[2] / 3;
    long long n_pairs_ll = (long long)insnum * insnum - insnum;
    int n_pairs = (n_pairs_ll > MAX_PAIRS) ? MAX_PAIRS : (int)n_pairs_ll;
    int n_words4 = (n_pairs + 3) / 4;

    float* out = (float*)d_out;

    // 1) scatter class bits (+ zero the output scalar)
    {
        int threads = 256;
        int blocks = (n_rel + threads - 1) / threads;
        scatter_kernel<<<blocks, threads>>>(rel_gt, n_rel, insnum, n_pairs, out);
    }

    // 2) focal loss + reduction + mask self-clean
    {
        int threads = 256;
        int blocks = (n_words4 + threads - 1) / threads;
        if (blocks > 2368) blocks = 2368;  // ~16 blocks/SM on 148 SMs
        loss_kernel<<<blocks, threads>>>(
            (const float4*)type_output, pred_w, out,
            n_words4, n_pairs, 1.0f / (float)n_pairs_ll);
    }
}